// round 6
// baseline (speedup 1.0000x reference)
#include <cuda_runtime.h>
#include <cuda_fp16.h>
#include <math.h>

// Problem constants: B=2, L=1024, E=1024, H=8, D=64, N_ITERS=20
#define NBH   16
#define LSEQ  1024
#define DH    64
#define EDIM  1024
#define HD    512
#define MROWS 2048
#define NITERS 20
#define NBLOCKS 148
#define MAXROWS 111
#define NR_TOT  16384

// SMEM layout of the fused kernel (bytes)
#define PS_BYTES (MAXROWS * 2048)          // P slice, swizzled, 227328
#define USF_OFF  PS_BYTES                  // 112 floats: row sums
#define USI_OFF  (USF_OFF + 448)           // 112 floats: u = 1/rowsum
#define VSH_OFF  (USI_OFF + 448)           // 1024 halfs: v staged
#define SMEM_SZ  (VSH_OFF + 2048)          // 230272 <= 232448

// ---------------- scratch (device globals) ----------------
__device__ __half g_xh [MROWS * EDIM];
__device__ __half g_wh [3 * HD * EDIM];
__device__ __half g_woh[EDIM * HD];
__device__ __half g_qh [NR_TOT * DH];
__device__ __half g_kh [NR_TOT * DH];
__device__ __half g_vh [NR_TOT * DH];
__device__ __half g_vt [NBH * DH * LSEQ];   // v_j * V^T  [bh][d][j]
__device__ __half g_ah [MROWS * HD];        // u*(P@V')   [b*L+l][h*64+d]
__device__ float  g_cs3[3][NBH * LSEQ];     // colsum triple buffer
__device__ unsigned g_count = 0;
__device__ volatile unsigned g_gen = 0;

// ---------------- helpers ----------------
__device__ __forceinline__ int row_start(int b) {
    return (b < 104) ? b * 111 : 11544 + (b - 104) * 110;
}
__device__ __forceinline__ void gsync() {
    __syncthreads();
    if (threadIdx.x == 0) {
        unsigned gen = g_gen;
        __threadfence();
        if (atomicAdd(&g_count, 1u) == NBLOCKS - 1) {
            g_count = 0;
            __threadfence();
            g_gen = gen + 1;
        } else {
            while (g_gen == gen) { }
        }
        __threadfence();
    }
    __syncthreads();
}
__device__ __forceinline__ void ldsm4(unsigned& r0, unsigned& r1,
                                      unsigned& r2, unsigned& r3, unsigned addr) {
    asm volatile("ldmatrix.sync.aligned.m8n8.x4.shared.b16 {%0,%1,%2,%3},[%4];\n"
                 : "=r"(r0), "=r"(r1), "=r"(r2), "=r"(r3) : "r"(addr));
}
__device__ __forceinline__ void ldsm4t(unsigned& r0, unsigned& r1,
                                       unsigned& r2, unsigned& r3, unsigned addr) {
    asm volatile("ldmatrix.sync.aligned.m8n8.x4.trans.shared.b16 {%0,%1,%2,%3},[%4];\n"
                 : "=r"(r0), "=r"(r1), "=r"(r2), "=r"(r3) : "r"(addr));
}
__device__ __forceinline__ void mma16816(float* c, const unsigned* a,
                                         unsigned b0, unsigned b1) {
    asm volatile(
        "mma.sync.aligned.m16n8k16.row.col.f32.f16.f16.f32 "
        "{%0,%1,%2,%3},{%4,%5,%6,%7},{%8,%9},{%0,%1,%2,%3};\n"
        : "+f"(c[0]), "+f"(c[1]), "+f"(c[2]), "+f"(c[3])
        : "r"(a[0]), "r"(a[1]), "r"(a[2]), "r"(a[3]), "r"(b0), "r"(b1));
}
// swizzled byte offset of (row, 16B-chunk) inside Ps
__device__ __forceinline__ unsigned sw_off(int row, int chunk) {
    return (unsigned)(row * 2048 + ((chunk ^ (row & 7)) << 4));
}
__device__ __forceinline__ unsigned packh2(float a, float b) {
    __half2 h = __floats2half2_rn(a, b);
    return *(unsigned*)&h;
}

// ============================================================================
// Generic 128x64 block HMMA GEMM (unchanged from R5).  A [M][K], B [N][K].
// ============================================================================
template <class Epi>
__device__ __forceinline__ void hgemm(const __half* __restrict__ A,
                                      const __half* __restrict__ Bn,
                                      int K, int m0, int n0, Epi epi)
{
    __shared__ __half As[128 * 40];
    __shared__ __half Bs[64 * 40];

    const int tid  = threadIdx.x;
    const int lane = tid & 31, warp = tid >> 5;
    const int wm = warp & 3, wn = warp >> 2;

    const int arow = tid >> 1, acol = (tid & 1) * 16;
    const int brow = tid >> 2, bcol = (tid & 3) * 8;
    const __half* Ag = A  + (m0 + arow) * K + acol;
    const __half* Bg = Bn + (n0 + brow) * K + bcol;

    uint4 ap0 = *(const uint4*)(Ag + 0);
    uint4 ap1 = *(const uint4*)(Ag + 8);
    uint4 bp  = *(const uint4*)(Bg);

    float acc[2][4][4] = {};

    const unsigned a_base0 = (unsigned)__cvta_generic_to_shared(
        &As[(wm * 32 + 0  + (lane & 15)) * 40 + ((lane >> 4) << 3)]);
    const unsigned a_base1 = (unsigned)__cvta_generic_to_shared(
        &As[(wm * 32 + 16 + (lane & 15)) * 40 + ((lane >> 4) << 3)]);

    for (int k0 = 0; k0 < K; k0 += 32) {
        *(uint4*)&As[arow * 40 + acol]     = ap0;
        *(uint4*)&As[arow * 40 + acol + 8] = ap1;
        *(uint4*)&Bs[brow * 40 + bcol]     = bp;
        __syncthreads();

        if (k0 + 32 < K) {
            ap0 = *(const uint4*)(Ag + k0 + 32);
            ap1 = *(const uint4*)(Ag + k0 + 40);
            bp  = *(const uint4*)(Bg + k0 + 32);
        }

        #pragma unroll
        for (int s = 0; s < 2; s++) {
            unsigned a0[4], a1[4];
            ldsm4(a0[0], a0[1], a0[2], a0[3], a_base0 + s * 32);
            ldsm4(a1[0], a1[1], a1[2], a1[3], a_base1 + s * 32);
            #pragma unroll
            for (int j = 0; j < 4; j++) {
                const __half* bp2 =
                    &Bs[(wn * 32 + j * 8 + (lane >> 2)) * 40 + s * 16 + (lane & 3) * 2];
                unsigned b0 = *(const unsigned*)bp2;
                unsigned b1 = *(const unsigned*)(bp2 + 8);
                mma16816(acc[0][j], a0, b0, b1);
                mma16816(acc[1][j], a1, b0, b1);
            }
        }
        __syncthreads();
    }

    const int g = lane >> 2, c2 = (lane & 3) * 2;
    #pragma unroll
    for (int f = 0; f < 2; f++)
        #pragma unroll
        for (int j = 0; j < 4; j++) {
            int rm = m0 + wm * 32 + f * 16 + g;
            int cn = n0 + wn * 32 + j * 8 + c2;
            epi(rm,     cn,     acc[f][j][0]);
            epi(rm,     cn + 1, acc[f][j][1]);
            epi(rm + 8, cn,     acc[f][j][2]);
            epi(rm + 8, cn + 1, acc[f][j][3]);
        }
}

struct EpiQKV {
    const float* bias; int z;
    __device__ void operator()(int m, int n, float v) const {
        int b = m >> 10, l = m & 1023, h = n >> 6, d = n & 63;
        int idx = (((b << 3) + h) << 16) + (l << 6) + d;
        float val = v + bias[n];
        if (z == 0)      g_qh[idx] = __float2half_rn(val);
        else if (z == 1) g_kh[idx] = __float2half_rn(val);
        else             g_vh[idx] = __float2half_rn(val);
    }
};
struct EpiOut {
    const float* bo; float* out;
    __device__ void operator()(int m, int n, float v) const {
        out[m * EDIM + n] = v + bo[n];
    }
};

__global__ __launch_bounds__(256) void qkv_h_kernel(
    const float* __restrict__ bq, const float* __restrict__ bk,
    const float* __restrict__ bv)
{
    const int z = blockIdx.z;
    const float* bias = (z == 0) ? bq : (z == 1) ? bk : bv;
    EpiQKV epi{bias, z};
    hgemm(g_xh, g_wh + z * (HD * EDIM), EDIM,
          blockIdx.y * 128, blockIdx.x * 64, epi);
}
__global__ __launch_bounds__(256) void out_h_kernel(
    const float* __restrict__ bo, float* __restrict__ out)
{
    EpiOut epi{bo, out};
    hgemm(g_ah, g_woh, HD, blockIdx.y * 128, blockIdx.x * 64, epi);
}

// ============================================================================
// conversion kernels
// ============================================================================
__global__ void conv_x_kernel(const float* __restrict__ x) {
    int idx = blockIdx.x * 256 + threadIdx.x;
    float4 v = ((const float4*)x)[idx];
    ((__half2*)g_xh)[2 * idx]     = __floats2half2_rn(v.x, v.y);
    ((__half2*)g_xh)[2 * idx + 1] = __floats2half2_rn(v.z, v.w);
}
__global__ void conv_w_kernel(const float* __restrict__ Wq,
                              const float* __restrict__ Wk,
                              const float* __restrict__ Wv,
                              const float* __restrict__ Wo)
{
    const int z = blockIdx.z;
    const float* src; __half* dst; int R, C;
    if (z < 3) { src = (z == 0) ? Wq : (z == 1) ? Wk : Wv;
                 dst = g_wh + z * (HD * EDIM); R = 1024; C = 512; }
    else       { src = Wo; dst = g_woh; R = 512; C = 1024; }
    const int r0 = blockIdx.y * 32, c0 = blockIdx.x * 32;
    if (r0 >= R || c0 >= C) return;
    __shared__ float t[32][33];
    for (int r = threadIdx.y; r < 32; r += 8)
        t[r][threadIdx.x] = src[(r0 + r) * C + c0 + threadIdx.x];
    __syncthreads();
    for (int r = threadIdx.y; r < 32; r += 8)
        dst[(c0 + r) * R + r0 + threadIdx.x] = __float2half_rn(t[threadIdx.x][r]);
}
__global__ void init_cs_kernel() {
    const int idx = blockIdx.x * 1024 + threadIdx.x;
    g_cs3[0][idx] = 1.0f;
    g_cs3[1][idx] = 0.0f;
}

// ============================================================================
// FUSED persistent kernel: P-build + 20 Sinkhorn iterations + attn@V,
// P lives only in SMEM.  grid 148, block 1024.
// ============================================================================
__global__ __launch_bounds__(1024, 1) void sinkhorn_fused()
{
    extern __shared__ char smem[];
    char*   PsB    = smem;
    float*  us_f   = (float*)(smem + USF_OFF);
    float*  us_inv = (float*)(smem + USI_OFF);
    __half* vsh    = (__half*)(smem + VSH_OFF);
    const unsigned ps_base = (unsigned)__cvta_generic_to_shared(PsB);

    const int blk = blockIdx.x;
    const int r0 = row_start(blk), r1 = row_start(blk + 1);
    const int nrows = r1 - r0;
    const int tid = threadIdx.x;
    const int warp = tid >> 5, lane = tid & 31;
    const int g = lane >> 2, c2 = (lane & 3) * 2;
    const int l15 = lane & 15, l16 = lane >> 4;

    const int bh0 = r0 >> 10;
    const int s_break = min(nrows, ((bh0 + 1) << 10) - r0);
    const int nseg = (s_break < nrows) ? 2 : 1;

    const int mt = warp >> 2;          // m-tile id 0..7
    const int kq = warp & 3;           // k quarter

    // ================= prologue: P slice = exp(Q K^T / 8) ==================
    for (int s = 0; s < nseg; s++) {
        const int s_lo = s ? s_break : 0;
        const int s_hi = s ? nrows : s_break;
        const int len = s_hi - s_lo;
        const int bh = bh0 + s;
        const int ntile = (len + 15) >> 4;
        if (mt < ntile) {
            const int rA = r0 + s_lo + mt * 16;
            unsigned a[4][4];
            #pragma unroll
            for (int kc = 0; kc < 4; kc++) {
                int rg0 = min(rA + g,     NR_TOT - 1);
                int rg1 = min(rA + 8 + g, NR_TOT - 1);
                a[kc][0] = *(const unsigned*)(g_qh + rg0 * 64 + kc * 16 + c2);
                a[kc][1] = *(const unsigned*)(g_qh + rg1 * 64 + kc * 16 + c2);
                a[kc][2] = *(const unsigned*)(g_qh + rg0 * 64 + kc * 16 + c2 + 8);
                a[kc][3] = *(const unsigned*)(g_qh + rg1 * 64 + kc * 16 + c2 + 8);
            }
            const __half* Kh = g_kh + (bh << 16);
            const int v0 = (mt * 16 + g) < len;
            const int v1 = (mt * 16 + 8 + g) < len;
            for (int nc = kq * 32; nc < kq * 32 + 32; nc++) {
                const int j0 = nc * 8;
                float c[4] = {0.f, 0.f, 0.f, 0.f};
                #pragma unroll
                for (int kc = 0; kc < 4; kc++) {
                    unsigned b0 = *(const unsigned*)(Kh + (j0 + g) * 64 + kc * 16 + c2);
                    unsigned b1 = *(const unsigned*)(Kh + (j0 + g) * 64 + kc * 16 + c2 + 8);
                    mma16816(c, a[kc], b0, b1);
                }
                unsigned h01 = packh2(__expf(c[0] * 0.125f), __expf(c[1] * 0.125f));
                unsigned h23 = packh2(__expf(c[2] * 0.125f), __expf(c[3] * 0.125f));
                const int lr0 = s_lo + mt * 16 + g;
                const int chunk = j0 >> 3;
                if (v0) *(unsigned*)(PsB + sw_off(lr0,     chunk) + c2 * 2) = h01;
                if (v1) *(unsigned*)(PsB + sw_off(lr0 + 8, chunk) + c2 * 2) = h23;
            }
        }
    }
    __syncthreads();

    // ================= Sinkhorn iterations ==================
    for (int it = 0; it < NITERS; it++) {
        const float* csR = g_cs3[it % 3];
        float*       csW = g_cs3[(it + 1) % 3];
        float*       csZ = g_cs3[(it + 2) % 3];

        for (int i = tid; i < nrows; i += 1024) csZ[r0 + i] = 0.0f;
        if (tid < 112) us_f[tid] = 0.0f;

        // ---- row phase: us_f[i] = sum_j P_ij * v_j  (tensor cores) ----
        for (int s = 0; s < nseg; s++) {
            const int s_lo = s ? s_break : 0;
            const int s_hi = s ? nrows : s_break;
            const int len = s_hi - s_lo;
            const int bh = bh0 + s;
            __syncthreads();
            vsh[tid] = __float2half_rn(1.0f / csR[(bh << 10) + tid]);
            __syncthreads();
            const int ntile = (len + 15) >> 4;
            if (mt < ntile) {
                float c[4] = {0.f, 0.f, 0.f, 0.f};
                const int rbase = s_lo + mt * 16 + l15;
                for (int kc = kq * 16; kc < kq * 16 + 16; kc++) {
                    const int k0 = kc * 16;
                    int rrow = min(rbase, s_hi - 1);
                    unsigned a0, a1, a2, a3;
                    ldsm4(a0, a1, a2, a3, ps_base + sw_off(rrow, (k0 >> 3) + l16));
                    unsigned aa[4] = {a0, a1, a2, a3};
                    unsigned b0 = *(const unsigned*)(vsh + k0 + c2);
                    unsigned b1 = *(const unsigned*)(vsh + k0 + c2 + 8);
                    mma16816(c, aa, b0, b1);
                }
                if ((lane & 3) == 0) {
                    if (mt * 16 + g < len)     atomicAdd(&us_f[s_lo + mt * 16 + g], c[0]);
                    if (mt * 16 + 8 + g < len) atomicAdd(&us_f[s_lo + mt * 16 + 8 + g], c[2]);
                }
            }
        }
        __syncthreads();
        if (tid < nrows) us_inv[tid] = 1.0f / us_f[tid];
        __syncthreads();

        // ---- col phase: csW[j] += sum_i u_i P_ij  (tensor cores) ----
        for (int cp = 0; cp < 2; cp++) {
            const int j0 = (warp + cp * 32) * 16;    // 16-col chunk
            for (int s = 0; s < nseg; s++) {
                const int s_lo = s ? s_break : 0;
                const int s_hi = s ? nrows : s_break;
                const int bh = bh0 + s;
                const int ntk = (s_hi - s_lo + 15) >> 4;
                float c0[4] = {0.f, 0.f, 0.f, 0.f};
                float c1[4] = {0.f, 0.f, 0.f, 0.f};
                for (int kt = 0; kt < ntk; kt++) {
                    const int k0 = s_lo + kt * 16;
                    const int ka = k0 + c2;
                    float f0 = (ka     < s_hi) ? us_inv[ka]     : 0.f;
                    float f1 = (ka + 1 < s_hi) ? us_inv[ka + 1] : 0.f;
                    float f2 = (ka + 8 < s_hi) ? us_inv[ka + 8] : 0.f;
                    float f3 = (ka + 9 < s_hi) ? us_inv[ka + 9] : 0.f;
                    unsigned a01 = packh2(f0, f1), a23 = packh2(f2, f3);
                    unsigned aa[4] = {a01, a01, a23, a23};
                    int rrow = min(k0 + l15, nrows - 1);
                    unsigned b0, b1, b2, b3;
                    ldsm4t(b0, b1, b2, b3, ps_base + sw_off(rrow, (j0 >> 3) + l16));
                    mma16816(c0, aa, b0, b1);
                    mma16816(c1, aa, b2, b3);
                }
                if (g == 0) {                      // lanes 0..3 hold row 0 of C
                    float* cw = csW + (bh << 10) + j0;
                    atomicAdd(cw + c2,         c0[0]);
                    atomicAdd(cw + c2 + 1,     c0[1]);
                    atomicAdd(cw + 8 + c2,     c1[0]);
                    atomicAdd(cw + 8 + c2 + 1, c1[1]);
                }
            }
        }
        gsync();
    }

    // ================= build g_vt = v_j * V^T for our rows =================
    {
        const float* csF = g_cs3[NITERS % 3];
        for (int idx = tid; idx < nrows * 64; idx += 1024) {
            int i = idx >> 6, d = idx & 63;
            int gr = r0 + i;
            int bh = gr >> 10, j = gr & 1023;
            float vf = 1.0f / csF[gr];
            float vv = __half2float(g_vh[(bh << 16) + (j << 6) + d]);
            g_vt[(bh << 16) + (d << 10) + j] = __float2half_rn(vf * vv);
        }
    }
    gsync();

    // ================= attn@V epilogue: out = u .* (P @ V') ================
    {
        const int dq = warp & 3;          // d quarter: d0 = dq*16
        const int d0 = dq * 16;
        for (int s = 0; s < nseg; s++) {
            const int s_lo = s ? s_break : 0;
            const int s_hi = s ? nrows : s_break;
            const int len = s_hi - s_lo;
            const int bh = bh0 + s;
            const int ntile = (len + 15) >> 4;
            if (mt >= ntile) continue;
            const __half* VT = g_vt + (bh << 16);
            float c0[4] = {0.f, 0.f, 0.f, 0.f};
            float c1[4] = {0.f, 0.f, 0.f, 0.f};
            const int rbase = s_lo + mt * 16 + l15;
            for (int kc = 0; kc < 64; kc++) {
                const int k0 = kc * 16;
                int rrow = min(rbase, s_hi - 1);
                unsigned a0, a1, a2, a3;
                ldsm4(a0, a1, a2, a3, ps_base + sw_off(rrow, (k0 >> 3) + l16));
                unsigned aa[4] = {a0, a1, a2, a3};
                unsigned b0 = *(const unsigned*)(VT + (d0 + g) * 1024 + k0 + c2);
                unsigned b1 = *(const unsigned*)(VT + (d0 + g) * 1024 + k0 + c2 + 8);
                mma16816(c0, aa, b0, b1);
                unsigned b2 = *(const unsigned*)(VT + (d0 + 8 + g) * 1024 + k0 + c2);
                unsigned b3 = *(const unsigned*)(VT + (d0 + 8 + g) * 1024 + k0 + c2 + 8);
                mma16816(c1, aa, b2, b3);
            }
            #pragma unroll
            for (int f = 0; f < 2; f++) {
                const int rl = mt * 16 + f * 8 + g;
                if (rl >= len) continue;
                const int gr = r0 + s_lo + rl;
                const float u = us_inv[s_lo + rl];
                const int bhh = gr >> 10, bb = bhh >> 3, hh = bhh & 7, ll = gr & 1023;
                __half* dst = g_ah + (bb * 1024 + ll) * 512 + hh * 64;
                float x0 = (f == 0) ? c0[0] : c0[2];
                float x1 = (f == 0) ? c0[1] : c0[3];
                float x2 = (f == 0) ? c1[0] : c1[2];
                float x3 = (f == 0) ? c1[1] : c1[3];
                *(unsigned*)(dst + d0 + c2)     = packh2(u * x0, u * x1);
                *(unsigned*)(dst + d0 + 8 + c2) = packh2(u * x2, u * x3);
            }
        }
    }
}

// ============================================================================
extern "C" void kernel_launch(void* const* d_in, const int* in_sizes, int n_in,
                              void* d_out, int out_size)
{
    const float* x  = (const float*)d_in[0];
    const float* Wq = (const float*)d_in[1];
    const float* bq = (const float*)d_in[2];
    const float* Wk = (const float*)d_in[3];
    const float* bk = (const float*)d_in[4];
    const float* Wv = (const float*)d_in[5];
    const float* bv = (const float*)d_in[6];
    const float* Wo = (const float*)d_in[7];
    const float* bo = (const float*)d_in[8];
    float* out = (float*)d_out;

    static int smem_set = 0;
    if (!smem_set) {
        cudaFuncSetAttribute(sinkhorn_fused,
                             cudaFuncAttributeMaxDynamicSharedMemorySize, SMEM_SZ);
        smem_set = 1;
    }

    conv_x_kernel<<<2048, 256>>>(x);
    conv_w_kernel<<<dim3(32, 32, 4), dim3(32, 8)>>>(Wq, Wk, Wv, Wo);

    qkv_h_kernel<<<dim3(8, 16, 3), 256>>>(bq, bk, bv);

    init_cs_kernel<<<16, 1024>>>();
    sinkhorn_fused<<<NBLOCKS, 1024, SMEM_SZ>>>();

    out_h_kernel<<<dim3(16, 16, 1), 256>>>(bo, out);
}

// round 7
// speedup vs baseline: 1.1258x; 1.1258x over previous
#include <cuda_runtime.h>
#include <cuda_fp16.h>
#include <math.h>

// Problem constants: B=2, L=1024, E=1024, H=8, D=64, N_ITERS=20
#define NBH   16
#define LSEQ  1024
#define DH    64
#define EDIM  1024
#define HD    512
#define MROWS 2048
#define NITERS 20
#define NBLOCKS 148
#define MAXROWS 111
#define NR_TOT  16384

// SMEM layout of sinkhorn_tc (bytes)
#define PS_BYTES (MAXROWS * 2048)          // swizzled P slice  227328
#define USF_OFF  PS_BYTES                  // 112 floats: row sums
#define USI_OFF  (USF_OFF + 448)           // 112 floats: u = 1/rowsum
#define VSH_OFF  (USI_OFF + 448)           // 1024 halfs: v staged
#define SMEM_SZ  (VSH_OFF + 2048)          // 230272

// ---------------- scratch (device globals) ----------------
__device__ __half g_xh [MROWS * EDIM];
__device__ __half g_wh [3 * HD * EDIM];
__device__ __half g_woh[EDIM * HD];
__device__ __half g_qh [NR_TOT * DH];
__device__ __half g_kh [NR_TOT * DH];
__device__ float  g_v  [NR_TOT * DH];       // V fp32 [bh][l][d]
__device__ __half g_vt [NBH * DH * LSEQ];   // v_j * V^T  [bh][d][j]
__device__ __half g_P  [NBH * LSEQ * LSEQ]; // 32 MB Gibbs kernel
__device__ __half g_ah [MROWS * HD];        // u*(P@V')   [b*L+l][h*64+d]
__device__ float  g_ur [NBH * LSEQ];
__device__ float  g_vc [NBH * LSEQ];
__device__ float  g_cs3[3][NBH * LSEQ];     // colsum triple buffer
__device__ unsigned g_count = 0;
__device__ volatile unsigned g_gen = 0;

// ---------------- helpers ----------------
__device__ __forceinline__ int row_start(int b) {
    return (b < 104) ? b * 111 : 11544 + (b - 104) * 110;
}
__device__ __forceinline__ void gsync() {
    __syncthreads();
    if (threadIdx.x == 0) {
        unsigned gen = g_gen;
        __threadfence();
        if (atomicAdd(&g_count, 1u) == NBLOCKS - 1) {
            g_count = 0;
            __threadfence();
            g_gen = gen + 1;
        } else {
            while (g_gen == gen) { }
        }
        __threadfence();
    }
    __syncthreads();
}
__device__ __forceinline__ void ldsm4(unsigned& r0, unsigned& r1,
                                      unsigned& r2, unsigned& r3, unsigned addr) {
    asm volatile("ldmatrix.sync.aligned.m8n8.x4.shared.b16 {%0,%1,%2,%3},[%4];\n"
                 : "=r"(r0), "=r"(r1), "=r"(r2), "=r"(r3) : "r"(addr));
}
__device__ __forceinline__ void ldsm4t(unsigned& r0, unsigned& r1,
                                       unsigned& r2, unsigned& r3, unsigned addr) {
    asm volatile("ldmatrix.sync.aligned.m8n8.x4.trans.shared.b16 {%0,%1,%2,%3},[%4];\n"
                 : "=r"(r0), "=r"(r1), "=r"(r2), "=r"(r3) : "r"(addr));
}
__device__ __forceinline__ void mma16816(float* c, const unsigned* a,
                                         unsigned b0, unsigned b1) {
    asm volatile(
        "mma.sync.aligned.m16n8k16.row.col.f32.f16.f16.f32 "
        "{%0,%1,%2,%3},{%4,%5,%6,%7},{%8,%9},{%0,%1,%2,%3};\n"
        : "+f"(c[0]), "+f"(c[1]), "+f"(c[2]), "+f"(c[3])
        : "r"(a[0]), "r"(a[1]), "r"(a[2]), "r"(a[3]), "r"(b0), "r"(b1));
}
__device__ __forceinline__ unsigned sw_off(int row, int chunk) {
    return (unsigned)(row * 2048 + ((chunk ^ (row & 7)) << 4));
}
__device__ __forceinline__ unsigned packh2(float a, float b) {
    __half2 h = __floats2half2_rn(a, b);
    return *(unsigned*)&h;
}

// ============================================================================
// Generic 128x64 block HMMA GEMM.  A [M][K] row-major fp16, B [N][K] fp16.
// 256 threads, warps 4(M) x 2(N).  Epi receives PAIRS (n, n+1).
// ============================================================================
template <class Epi>
__device__ __forceinline__ void hgemm(const __half* __restrict__ A,
                                      const __half* __restrict__ Bn,
                                      int K, int m0, int n0, Epi epi)
{
    __shared__ __half As[128 * 40];
    __shared__ __half Bs[64 * 40];

    const int tid  = threadIdx.x;
    const int lane = tid & 31, warp = tid >> 5;
    const int wm = warp & 3, wn = warp >> 2;

    const int arow = tid >> 1, acol = (tid & 1) * 16;
    const int brow = tid >> 2, bcol = (tid & 3) * 8;
    const __half* Ag = A  + (m0 + arow) * K + acol;
    const __half* Bg = Bn + (n0 + brow) * K + bcol;

    uint4 ap0 = *(const uint4*)(Ag + 0);
    uint4 ap1 = *(const uint4*)(Ag + 8);
    uint4 bp  = *(const uint4*)(Bg);

    float acc[2][4][4] = {};

    const unsigned a_base0 = (unsigned)__cvta_generic_to_shared(
        &As[(wm * 32 + 0  + (lane & 15)) * 40 + ((lane >> 4) << 3)]);
    const unsigned a_base1 = (unsigned)__cvta_generic_to_shared(
        &As[(wm * 32 + 16 + (lane & 15)) * 40 + ((lane >> 4) << 3)]);

    for (int k0 = 0; k0 < K; k0 += 32) {
        *(uint4*)&As[arow * 40 + acol]     = ap0;
        *(uint4*)&As[arow * 40 + acol + 8] = ap1;
        *(uint4*)&Bs[brow * 40 + bcol]     = bp;
        __syncthreads();

        if (k0 + 32 < K) {
            ap0 = *(const uint4*)(Ag + k0 + 32);
            ap1 = *(const uint4*)(Ag + k0 + 40);
            bp  = *(const uint4*)(Bg + k0 + 32);
        }

        #pragma unroll
        for (int s = 0; s < 2; s++) {
            unsigned a0[4], a1[4];
            ldsm4(a0[0], a0[1], a0[2], a0[3], a_base0 + s * 32);
            ldsm4(a1[0], a1[1], a1[2], a1[3], a_base1 + s * 32);
            #pragma unroll
            for (int j = 0; j < 4; j++) {
                const __half* bp2 =
                    &Bs[(wn * 32 + j * 8 + (lane >> 2)) * 40 + s * 16 + (lane & 3) * 2];
                unsigned b0 = *(const unsigned*)bp2;
                unsigned b1 = *(const unsigned*)(bp2 + 8);
                mma16816(acc[0][j], a0, b0, b1);
                mma16816(acc[1][j], a1, b0, b1);
            }
        }
        __syncthreads();
    }

    const int g = lane >> 2, c2 = (lane & 3) * 2;
    #pragma unroll
    for (int f = 0; f < 2; f++)
        #pragma unroll
        for (int j = 0; j < 4; j++) {
            int rm = m0 + wm * 32 + f * 16 + g;
            int cn = n0 + wn * 32 + j * 8 + c2;
            epi(rm,     cn, acc[f][j][0], acc[f][j][1]);
            epi(rm + 8, cn, acc[f][j][2], acc[f][j][3]);
        }
}

// ---------------- epilogues (paired, vector stores) ----------------
struct EpiQKV {
    const float* bias; int z;
    __device__ void operator()(int m, int n, float v0, float v1) const {
        int b = m >> 10, l = m & 1023, h = n >> 6, d = n & 63;
        int idx = (((b << 3) + h) << 16) + (l << 6) + d;
        float a0 = v0 + bias[n], a1 = v1 + bias[n + 1];
        if (z == 0)      *(unsigned*)(g_qh + idx) = packh2(a0, a1);
        else if (z == 1) *(unsigned*)(g_kh + idx) = packh2(a0, a1);
        else             { float2 f2 = {a0, a1}; *(float2*)(g_v + idx) = f2; }
    }
};
struct EpiP {
    __half* P;
    __device__ void operator()(int m, int n, float v0, float v1) const {
        *(unsigned*)(P + m * LSEQ + n) =
            packh2(__expf(v0 * 0.125f), __expf(v1 * 0.125f));
    }
};
struct EpiAttnV {
    int bh;
    __device__ void operator()(int m, int n, float v0, float v1) const {
        float u = g_ur[(bh << 10) + m];
        int b = bh >> 3, h = bh & 7;
        *(unsigned*)(g_ah + (b * LSEQ + m) * HD + h * DH + n) =
            packh2(u * v0, u * v1);
    }
};
struct EpiOut {
    const float* bo; float* out;
    __device__ void operator()(int m, int n, float v0, float v1) const {
        float2 f2 = {v0 + bo[n], v1 + bo[n + 1]};
        *(float2*)(out + m * EDIM + n) = f2;
    }
};

// ---------------- GEMM kernels ----------------
__global__ __launch_bounds__(256) void qkv_h_kernel(
    const float* __restrict__ bq, const float* __restrict__ bk,
    const float* __restrict__ bv)
{
    const int z = blockIdx.z;
    const float* bias = (z == 0) ? bq : (z == 1) ? bk : bv;
    EpiQKV epi{bias, z};
    hgemm(g_xh, g_wh + z * (HD * EDIM), EDIM,
          blockIdx.y * 128, blockIdx.x * 64, epi);
}
__global__ __launch_bounds__(256) void p_h_kernel()
{
    const int bh = blockIdx.z;
    EpiP epi{g_P + ((size_t)bh << 20)};
    hgemm(g_qh + (bh << 16), g_kh + (bh << 16), DH,
          blockIdx.y * 128, blockIdx.x * 64, epi);
}
__global__ __launch_bounds__(256) void attnv_h_kernel()
{
    const int bh = blockIdx.z;
    EpiAttnV epi{bh};
    hgemm(g_P + ((size_t)bh << 20), g_vt + (bh << 16), LSEQ,
          blockIdx.y * 128, blockIdx.x * 64, epi);
}
__global__ __launch_bounds__(256) void out_h_kernel(
    const float* __restrict__ bo, float* __restrict__ out)
{
    EpiOut epi{bo, out};
    hgemm(g_ah, g_woh, HD, blockIdx.y * 128, blockIdx.x * 64, epi);
}

// ============================================================================
// conversion kernels
// ============================================================================
__global__ void conv_x_kernel(const float* __restrict__ x) {
    int idx = blockIdx.x * 256 + threadIdx.x;
    float4 v = ((const float4*)x)[idx];
    ((__half2*)g_xh)[2 * idx]     = __floats2half2_rn(v.x, v.y);
    ((__half2*)g_xh)[2 * idx + 1] = __floats2half2_rn(v.z, v.w);
}
__global__ void conv_w_kernel(const float* __restrict__ Wq,
                              const float* __restrict__ Wk,
                              const float* __restrict__ Wv,
                              const float* __restrict__ Wo)
{
    const int z = blockIdx.z;
    const float* src; __half* dst; int R, C;
    if (z < 3) { src = (z == 0) ? Wq : (z == 1) ? Wk : Wv;
                 dst = g_wh + z * (HD * EDIM); R = 1024; C = 512; }
    else       { src = Wo; dst = g_woh; R = 512; C = 1024; }
    const int r0 = blockIdx.y * 32, c0 = blockIdx.x * 32;
    if (r0 >= R || c0 >= C) return;
    __shared__ float t[32][33];
    for (int r = threadIdx.y; r < 32; r += 8)
        t[r][threadIdx.x] = src[(r0 + r) * C + c0 + threadIdx.x];
    __syncthreads();
    for (int r = threadIdx.y; r < 32; r += 8)
        dst[(c0 + r) * R + r0 + threadIdx.x] = __float2half_rn(t[threadIdx.x][r]);
}
// V'^T: g_vt[bh][d][j] = fp16( v_j * V[bh][j][d] )
__global__ void conv_vt_kernel()
{
    const int bh = blockIdx.z;
    const int j0 = blockIdx.x * 32, d0 = blockIdx.y * 32;
    __shared__ float t[32][33];
    for (int r = threadIdx.y; r < 32; r += 8)
        t[r][threadIdx.x] = g_v[(bh << 16) + ((j0 + r) << 6) + d0 + threadIdx.x];
    __syncthreads();
    for (int r = threadIdx.y; r < 32; r += 8) {
        int d = d0 + r, j = j0 + threadIdx.x;
        g_vt[(bh << 16) + (d << 10) + j] =
            __float2half_rn(g_vc[(bh << 10) + j] * t[threadIdx.x][r]);
    }
}
__global__ void init_cs_kernel() {
    const int idx = blockIdx.x * 1024 + threadIdx.x;
    g_cs3[0][idx] = 1.0f;
    g_cs3[1][idx] = 0.0f;
}

// ============================================================================
// Persistent Sinkhorn with tensor-core phases.  P loaded from global into
// swizzled SMEM once.  grid 148, block 1024.
// ============================================================================
__global__ __launch_bounds__(1024, 1) void sinkhorn_tc()
{
    extern __shared__ char smem[];
    char*   PsB    = smem;
    float*  us_f   = (float*)(smem + USF_OFF);
    float*  us_inv = (float*)(smem + USI_OFF);
    __half* vsh    = (__half*)(smem + VSH_OFF);
    const unsigned ps_base = (unsigned)__cvta_generic_to_shared(PsB);

    const int blk = blockIdx.x;
    const int r0 = row_start(blk), r1 = row_start(blk + 1);
    const int nrows = r1 - r0;
    const int tid = threadIdx.x;
    const int warp = tid >> 5, lane = tid & 31;
    const int g = lane >> 2, c2 = (lane & 3) * 2;
    const int l15 = lane & 15, l16 = lane >> 4;

    const int bh0 = r0 >> 10;
    const int s_break = min(nrows, ((bh0 + 1) << 10) - r0);
    const int nseg = (s_break < nrows) ? 2 : 1;
    const int mt = warp >> 2;          // m-tile 0..7
    const int kq = warp & 3;           // k quarter

    // ---- load P slice (row-major global -> swizzled SMEM), once ----
    for (int idx = tid; idx < nrows * 128; idx += 1024) {
        int row = idx >> 7, chunk = idx & 127;
        uint4 v = *(const uint4*)(g_P + ((size_t)(r0 + row) << 10) + chunk * 8);
        *(uint4*)(PsB + sw_off(row, chunk)) = v;
    }
    __syncthreads();

    for (int it = 0; it < NITERS; it++) {
        const float* csR = g_cs3[it % 3];
        float*       csW = g_cs3[(it + 1) % 3];
        float*       csZ = g_cs3[(it + 2) % 3];

        for (int i = tid; i < nrows; i += 1024) csZ[r0 + i] = 0.0f;
        if (tid < 112) us_f[tid] = 0.0f;

        // ---- row phase: us_f[i] = sum_j P_ij * v_j  (HMMA) ----
        for (int s = 0; s < nseg; s++) {
            const int s_lo = s ? s_break : 0;
            const int s_hi = s ? nrows : s_break;
            const int len = s_hi - s_lo;
            const int bh = bh0 + s;
            __syncthreads();
            vsh[tid] = __float2half_rn(1.0f / csR[(bh << 10) + tid]);
            __syncthreads();
            const int ntile = (len + 15) >> 4;
            if (mt < ntile) {
                float c[4] = {0.f, 0.f, 0.f, 0.f};
                const int rbase = s_lo + mt * 16 + l15;
                for (int kc = kq * 16; kc < kq * 16 + 16; kc++) {
                    const int k0 = kc * 16;
                    int rrow = min(rbase, s_hi - 1);
                    unsigned a0, a1, a2, a3;
                    ldsm4(a0, a1, a2, a3, ps_base + sw_off(rrow, (k0 >> 3) + l16));
                    unsigned aa[4] = {a0, a1, a2, a3};
                    unsigned b0 = *(const unsigned*)(vsh + k0 + c2);
                    unsigned b1 = *(const unsigned*)(vsh + k0 + c2 + 8);
                    mma16816(c, aa, b0, b1);
                }
                if ((lane & 3) == 0) {
                    if (mt * 16 + g < len)
                        atomicAdd(&us_f[s_lo + mt * 16 + g], c[0]);
                    if (mt * 16 + 8 + g < len)
                        atomicAdd(&us_f[s_lo + mt * 16 + 8 + g], c[2]);
                }
            }
        }
        __syncthreads();
        if (tid < nrows) us_inv[tid] = 1.0f / us_f[tid];
        __syncthreads();

        // ---- col phase: csW[j] += sum_i u_i P_ij  (HMMA, trans ldmatrix) ----
        for (int cp = 0; cp < 2; cp++) {
            const int j0 = (warp + cp * 32) * 16;
            for (int s = 0; s < nseg; s++) {
                const int s_lo = s ? s_break : 0;
                const int s_hi = s ? nrows : s_break;
                const int bh = bh0 + s;
                const int ntk = (s_hi - s_lo + 15) >> 4;
                float c0[4] = {0.f, 0.f, 0.f, 0.f};
                float c1[4] = {0.f, 0.f, 0.f, 0.f};
                for (int kt = 0; kt < ntk; kt++) {
                    const int k0 = s_lo + kt * 16;
                    const int ka = k0 + c2;
                    float f0 = (ka     < s_hi) ? us_inv[ka]     : 0.f;
                    float f1 = (ka + 1 < s_hi) ? us_inv[ka + 1] : 0.f;
                    float f2 = (ka + 8 < s_hi) ? us_inv[ka + 8] : 0.f;
                    float f3 = (ka + 9 < s_hi) ? us_inv[ka + 9] : 0.f;
                    unsigned a01 = packh2(f0, f1), a23 = packh2(f2, f3);
                    unsigned aa[4] = {a01, a01, a23, a23};
                    int rrow = min(k0 + l15, nrows - 1);
                    unsigned b0, b1, b2, b3;
                    ldsm4t(b0, b1, b2, b3, ps_base + sw_off(rrow, (j0 >> 3) + l16));
                    mma16816(c0, aa, b0, b1);
                    mma16816(c1, aa, b2, b3);
                }
                if (g == 0) {
                    float* cw = csW + (bh << 10) + j0;
                    atomicAdd(cw + c2,         c0[0]);
                    atomicAdd(cw + c2 + 1,     c0[1]);
                    atomicAdd(cw + 8 + c2,     c1[0]);
                    atomicAdd(cw + 8 + c2 + 1, c1[1]);
                }
            }
        }
        gsync();
    }

    // final potentials: u from last row phase, v = 1/colsum(buf 20%3)
    const float* csF = g_cs3[NITERS % 3];
    for (int i = tid; i < nrows; i += 1024) {
        g_ur[r0 + i] = us_inv[i];
        g_vc[r0 + i] = 1.0f / csF[r0 + i];
    }
}

// ============================================================================
extern "C" void kernel_launch(void* const* d_in, const int* in_sizes, int n_in,
                              void* d_out, int out_size)
{
    const float* x  = (const float*)d_in[0];
    const float* Wq = (const float*)d_in[1];
    const float* bq = (const float*)d_in[2];
    const float* Wk = (const float*)d_in[3];
    const float* bk = (const float*)d_in[4];
    const float* Wv = (const float*)d_in[5];
    const float* bv = (const float*)d_in[6];
    const float* Wo = (const float*)d_in[7];
    const float* bo = (const float*)d_in[8];
    float* out = (float*)d_out;

    static int smem_set = 0;
    if (!smem_set) {
        cudaFuncSetAttribute(sinkhorn_tc,
                             cudaFuncAttributeMaxDynamicSharedMemorySize, SMEM_SZ);
        smem_set = 1;
    }

    conv_x_kernel<<<2048, 256>>>(x);
    conv_w_kernel<<<dim3(32, 32, 4), dim3(32, 8)>>>(Wq, Wk, Wv, Wo);

    qkv_h_kernel<<<dim3(8, 16, 3), 256>>>(bq, bk, bv);
    p_h_kernel<<<dim3(16, 8, NBH), 256>>>();

    init_cs_kernel<<<16, 1024>>>();
    sinkhorn_tc<<<NBLOCKS, 1024, SMEM_SZ>>>();

    conv_vt_kernel<<<dim3(32, 2, NBH), dim3(32, 8)>>>();
    attnv_h_kernel<<<dim3(1, 8, NBH), 256>>>();
    out_h_kernel<<<dim3(16, 16, 1), 256>>>(bo, out);
}

// round 8
// speedup vs baseline: 1.1956x; 1.0620x over previous
#include <cuda_runtime.h>
#include <cuda_fp16.h>
#include <math.h>

// Problem constants: B=2, L=1024, E=1024, H=8, D=64, N_ITERS=20
#define NBH   16
#define LSEQ  1024
#define DH    64
#define EDIM  1024
#define HD    512
#define MROWS 2048
#define NITERS 20
#define NBLOCKS 148
#define MAXROWS 111
#define NR_TOT  16384

// SMEM layout of sinkhorn_tc (bytes)
#define PS_BYTES (MAXROWS * 2048)
#define USF_OFF  PS_BYTES
#define USI_OFF  (USF_OFF + 448)
#define VSH_OFF  (USI_OFF + 448)
#define SMEM_SZ  (VSH_OFF + 2048)

// ---------------- scratch (device globals) ----------------
__device__ __half g_xh [MROWS * EDIM];
__device__ __half g_wh [3 * HD * EDIM];
__device__ __half g_woh[EDIM * HD];
__device__ __half g_qh [NR_TOT * DH];
__device__ __half g_kh [NR_TOT * DH];
__device__ float  g_v  [NR_TOT * DH];
__device__ __half g_vt [NBH * DH * LSEQ];
__device__ __half g_P  [NBH * LSEQ * LSEQ];
__device__ __half g_ah [MROWS * HD];
__device__ float  g_ur [NBH * LSEQ];
__device__ float  g_cs3[3][NBH * LSEQ];
__device__ unsigned g_count = 0;
__device__ volatile unsigned g_gen = 0;

// ---------------- helpers ----------------
__device__ __forceinline__ int row_start(int b) {
    return (b < 104) ? b * 111 : 11544 + (b - 104) * 110;
}
__device__ __forceinline__ void gsync() {
    __syncthreads();
    if (threadIdx.x == 0) {
        unsigned gen = g_gen;
        __threadfence();
        if (atomicAdd(&g_count, 1u) == NBLOCKS - 1) {
            g_count = 0;
            __threadfence();
            g_gen = gen + 1;
        } else {
            while (g_gen == gen) { __nanosleep(32); }
        }
        __threadfence();
    }
    __syncthreads();
}
__device__ __forceinline__ void ldsm4(unsigned& r0, unsigned& r1,
                                      unsigned& r2, unsigned& r3, unsigned addr) {
    asm volatile("ldmatrix.sync.aligned.m8n8.x4.shared.b16 {%0,%1,%2,%3},[%4];\n"
                 : "=r"(r0), "=r"(r1), "=r"(r2), "=r"(r3) : "r"(addr));
}
__device__ __forceinline__ void ldsm4t(unsigned& r0, unsigned& r1,
                                       unsigned& r2, unsigned& r3, unsigned addr) {
    asm volatile("ldmatrix.sync.aligned.m8n8.x4.trans.shared.b16 {%0,%1,%2,%3},[%4];\n"
                 : "=r"(r0), "=r"(r1), "=r"(r2), "=r"(r3) : "r"(addr));
}
__device__ __forceinline__ void mma16816(float* c, const unsigned* a,
                                         unsigned b0, unsigned b1) {
    asm volatile(
        "mma.sync.aligned.m16n8k16.row.col.f32.f16.f16.f32 "
        "{%0,%1,%2,%3},{%4,%5,%6,%7},{%8,%9},{%0,%1,%2,%3};\n"
        : "+f"(c[0]), "+f"(c[1]), "+f"(c[2]), "+f"(c[3])
        : "r"(a[0]), "r"(a[1]), "r"(a[2]), "r"(a[3]), "r"(b0), "r"(b1));
}
__device__ __forceinline__ unsigned sw_off(int row, int chunk) {
    return (unsigned)(row * 2048 + ((chunk ^ (row & 7)) << 4));
}
__device__ __forceinline__ unsigned packh2(float a, float b) {
    __half2 h = __floats2half2_rn(a, b);
    return *(unsigned*)&h;
}
__device__ __forceinline__ void cp16(void* smem_dst, const void* gsrc) {
    unsigned d = (unsigned)__cvta_generic_to_shared(smem_dst);
    asm volatile("cp.async.ca.shared.global [%0], [%1], 16;\n" :: "r"(d), "l"(gsrc));
}
__device__ __forceinline__ void cp_commit() {
    asm volatile("cp.async.commit_group;\n");
}
template <int N> __device__ __forceinline__ void cp_wait() {
    asm volatile("cp.async.wait_group %0;\n" :: "n"(N));
}

// ============================================================================
// 128x64 block HMMA GEMM with 2-stage cp.async pipeline.
// A [M][K] row-major fp16, B [N][K] fp16.  256 threads, warps 4(M) x 2(N).
// Epi receives PAIRS (n, n+1).  K % 32 == 0.
// ============================================================================
template <class Epi>
__device__ __forceinline__ void hgemm(const __half* __restrict__ A,
                                      const __half* __restrict__ Bn,
                                      int K, int m0, int n0, Epi epi)
{
    __shared__ __half As[2][128 * 40];
    __shared__ __half Bs[2][64 * 40];

    const int tid  = threadIdx.x;
    const int lane = tid & 31, warp = tid >> 5;
    const int wm = warp & 3, wn = warp >> 2;

    const int arow = tid >> 1, acol = (tid & 1) * 16;
    const int brow = tid >> 2, bcol = (tid & 3) * 8;
    const __half* Ag = A  + (m0 + arow) * K + acol;
    const __half* Bg = Bn + (n0 + brow) * K + bcol;

    float acc[2][4][4] = {};

    const unsigned a_off0 = (unsigned)__cvta_generic_to_shared(
        &As[0][(wm * 32 + 0  + (lane & 15)) * 40 + ((lane >> 4) << 3)]);
    const unsigned a_off1 = (unsigned)__cvta_generic_to_shared(
        &As[0][(wm * 32 + 16 + (lane & 15)) * 40 + ((lane >> 4) << 3)]);
    const unsigned abuf = 128 * 40 * 2;   // bytes per A buffer

    // prologue: stage 0
    cp16(&As[0][arow * 40 + acol],     Ag);
    cp16(&As[0][arow * 40 + acol + 8], Ag + 8);
    cp16(&Bs[0][brow * 40 + bcol],     Bg);
    cp_commit();

    const int KT = K >> 5;
    for (int kt = 0; kt < KT; kt++) {
        const int buf = kt & 1;
        if (kt + 1 < KT) {
            const int nb = buf ^ 1;
            cp16(&As[nb][arow * 40 + acol],     Ag + (kt + 1) * 32);
            cp16(&As[nb][arow * 40 + acol + 8], Ag + (kt + 1) * 32 + 8);
            cp16(&Bs[nb][brow * 40 + bcol],     Bg + (kt + 1) * 32);
            cp_commit();
            cp_wait<1>();
        } else {
            cp_wait<0>();
        }
        __syncthreads();

        #pragma unroll
        for (int s = 0; s < 2; s++) {
            unsigned a0[4], a1[4];
            ldsm4(a0[0], a0[1], a0[2], a0[3], a_off0 + buf * abuf + s * 32);
            ldsm4(a1[0], a1[1], a1[2], a1[3], a_off1 + buf * abuf + s * 32);
            #pragma unroll
            for (int j = 0; j < 4; j++) {
                const __half* bp2 =
                    &Bs[buf][(wn * 32 + j * 8 + (lane >> 2)) * 40 + s * 16 + (lane & 3) * 2];
                unsigned b0 = *(const unsigned*)bp2;
                unsigned b1 = *(const unsigned*)(bp2 + 8);
                mma16816(acc[0][j], a0, b0, b1);
                mma16816(acc[1][j], a1, b0, b1);
            }
        }
        __syncthreads();
    }

    const int g = lane >> 2, c2 = (lane & 3) * 2;
    #pragma unroll
    for (int f = 0; f < 2; f++)
        #pragma unroll
        for (int j = 0; j < 4; j++) {
            int rm = m0 + wm * 32 + f * 16 + g;
            int cn = n0 + wn * 32 + j * 8 + c2;
            epi(rm,     cn, acc[f][j][0], acc[f][j][1]);
            epi(rm + 8, cn, acc[f][j][2], acc[f][j][3]);
        }
}

// ---------------- epilogues ----------------
struct EpiQKV {
    const float* bias; int z;
    __device__ void operator()(int m, int n, float v0, float v1) const {
        int b = m >> 10, l = m & 1023, h = n >> 6, d = n & 63;
        int idx = (((b << 3) + h) << 16) + (l << 6) + d;
        float a0 = v0 + bias[n], a1 = v1 + bias[n + 1];
        if (z == 0)      *(unsigned*)(g_qh + idx) = packh2(a0, a1);
        else if (z == 1) *(unsigned*)(g_kh + idx) = packh2(a0, a1);
        else             { float2 f2 = {a0, a1}; *(float2*)(g_v + idx) = f2; }
    }
};
struct EpiP {
    __half* P;
    __device__ void operator()(int m, int n, float v0, float v1) const {
        *(unsigned*)(P + m * LSEQ + n) =
            packh2(__expf(v0 * 0.125f), __expf(v1 * 0.125f));
    }
};
struct EpiAttnV {
    int bh;
    __device__ void operator()(int m, int n, float v0, float v1) const {
        float u = g_ur[(bh << 10) + m];
        int b = bh >> 3, h = bh & 7;
        *(unsigned*)(g_ah + (b * LSEQ + m) * HD + h * DH + n) =
            packh2(u * v0, u * v1);
    }
};
struct EpiOut {
    const float* bo; float* out;
    __device__ void operator()(int m, int n, float v0, float v1) const {
        float2 f2 = {v0 + bo[n], v1 + bo[n + 1]};
        *(float2*)(out + m * EDIM + n) = f2;
    }
};

// ---------------- GEMM kernels ----------------
__global__ __launch_bounds__(256) void qkv_h_kernel(
    const float* __restrict__ bq, const float* __restrict__ bk,
    const float* __restrict__ bv)
{
    const int z = blockIdx.z;
    const float* bias = (z == 0) ? bq : (z == 1) ? bk : bv;
    EpiQKV epi{bias, z};
    hgemm(g_xh, g_wh + z * (HD * EDIM), EDIM,
          blockIdx.y * 128, blockIdx.x * 64, epi);
}
__global__ __launch_bounds__(256) void p_h_kernel()
{
    const int bh = blockIdx.z;
    EpiP epi{g_P + ((size_t)bh << 20)};
    hgemm(g_qh + (bh << 16), g_kh + (bh << 16), DH,
          blockIdx.y * 128, blockIdx.x * 64, epi);
}
__global__ __launch_bounds__(256) void attnv_h_kernel()
{
    const int bh = blockIdx.z;
    EpiAttnV epi{bh};
    hgemm(g_P + ((size_t)bh << 20), g_vt + (bh << 16), LSEQ,
          blockIdx.y * 128, blockIdx.x * 64, epi);
}
__global__ __launch_bounds__(256) void out_h_kernel(
    const float* __restrict__ bo, float* __restrict__ out)
{
    EpiOut epi{bo, out};
    hgemm(g_ah, g_woh, HD, blockIdx.y * 128, blockIdx.x * 64, epi);
}

// ============================================================================
// fused conversions + init.  1D grid of 6208 blocks x 256 threads:
//   [0, 2048)    : x -> fp16
//   [2048, 6144) : weight transpose-convert (z = (b-2048)>>10)
//   [6144, 6208) : colsum buffer init
// ============================================================================
__global__ __launch_bounds__(256) void conv_all(
    const float* __restrict__ x,
    const float* __restrict__ Wq, const float* __restrict__ Wk,
    const float* __restrict__ Wv, const float* __restrict__ Wo)
{
    __shared__ float t[32][33];
    const int b = blockIdx.x;
    const int tid = threadIdx.x;

    if (b < 2048) {
        int idx = b * 256 + tid;
        float4 v = ((const float4*)x)[idx];
        ((__half2*)g_xh)[2 * idx]     = __floats2half2_rn(v.x, v.y);
        ((__half2*)g_xh)[2 * idx + 1] = __floats2half2_rn(v.z, v.w);
    } else if (b < 6144) {
        const int bb = b - 2048;
        const int z = bb >> 10, rem = bb & 1023;
        const float* src; __half* dst; int R, C;
        if (z < 3) { src = (z == 0) ? Wq : (z == 1) ? Wk : Wv;
                     dst = g_wh + z * (HD * EDIM); R = 1024; C = 512; }
        else       { src = Wo; dst = g_woh; R = 512; C = 1024; }
        const int r0 = (rem >> 5) * 32, c0 = (rem & 31) * 32;
        if (r0 < R && c0 < C) {
            const int tx = tid & 31, ty = tid >> 5;
            for (int r = ty; r < 32; r += 8)
                t[r][tx] = src[(r0 + r) * C + c0 + tx];
            __syncthreads();
            for (int r = ty; r < 32; r += 8)
                dst[(c0 + r) * R + r0 + tx] = __float2half_rn(t[tx][r]);
        }
    } else {
        int idx = (b - 6144) * 256 + tid;
        g_cs3[0][idx] = 1.0f;
        g_cs3[1][idx] = 0.0f;
    }
}

// ============================================================================
// Persistent Sinkhorn, tensor-core phases, v_j*V^T built in the tail.
// grid 148, block 1024.
// ============================================================================
__global__ __launch_bounds__(1024, 1) void sinkhorn_tc()
{
    extern __shared__ char smem[];
    char*   PsB    = smem;
    float*  us_f   = (float*)(smem + USF_OFF);
    float*  us_inv = (float*)(smem + USI_OFF);
    __half* vsh    = (__half*)(smem + VSH_OFF);
    const unsigned ps_base = (unsigned)__cvta_generic_to_shared(PsB);

    const int blk = blockIdx.x;
    const int r0 = row_start(blk), r1 = row_start(blk + 1);
    const int nrows = r1 - r0;
    const int tid = threadIdx.x;
    const int warp = tid >> 5, lane = tid & 31;
    const int g = lane >> 2, c2 = (lane & 3) * 2;
    const int l15 = lane & 15, l16 = lane >> 4;

    const int bh0 = r0 >> 10;
    const int s_break = min(nrows, ((bh0 + 1) << 10) - r0);
    const int nseg = (s_break < nrows) ? 2 : 1;
    const int mt = warp >> 2;
    const int kq = warp & 3;

    // ---- load P slice (row-major global -> swizzled SMEM), once ----
    for (int idx = tid; idx < nrows * 128; idx += 1024) {
        int row = idx >> 7, chunk = idx & 127;
        uint4 v = *(const uint4*)(g_P + ((size_t)(r0 + row) << 10) + chunk * 8);
        *(uint4*)(PsB + sw_off(row, chunk)) = v;
    }
    __syncthreads();

    for (int it = 0; it < NITERS; it++) {
        const float* csR = g_cs3[it % 3];
        float*       csW = g_cs3[(it + 1) % 3];
        float*       csZ = g_cs3[(it + 2) % 3];

        for (int i = tid; i < nrows; i += 1024) csZ[r0 + i] = 0.0f;
        if (tid < 112) us_f[tid] = 0.0f;

        // ---- row phase: us_f[i] = sum_j P_ij * v_j ----
        for (int s = 0; s < nseg; s++) {
            const int s_lo = s ? s_break : 0;
            const int s_hi = s ? nrows : s_break;
            const int len = s_hi - s_lo;
            const int bh = bh0 + s;
            __syncthreads();
            vsh[tid] = __float2half_rn(1.0f / csR[(bh << 10) + tid]);
            __syncthreads();
            const int ntile = (len + 15) >> 4;
            if (mt < ntile) {
                float c[4] = {0.f, 0.f, 0.f, 0.f};
                const int rbase = s_lo + mt * 16 + l15;
                for (int kc = kq * 16; kc < kq * 16 + 16; kc++) {
                    const int k0 = kc * 16;
                    int rrow = min(rbase, s_hi - 1);
                    unsigned a0, a1, a2, a3;
                    ldsm4(a0, a1, a2, a3, ps_base + sw_off(rrow, (k0 >> 3) + l16));
                    unsigned aa[4] = {a0, a1, a2, a3};
                    unsigned b0 = *(const unsigned*)(vsh + k0 + c2);
                    unsigned b1 = *(const unsigned*)(vsh + k0 + c2 + 8);
                    mma16816(c, aa, b0, b1);
                }
                if ((lane & 3) == 0) {
                    if (mt * 16 + g < len)
                        atomicAdd(&us_f[s_lo + mt * 16 + g], c[0]);
                    if (mt * 16 + 8 + g < len)
                        atomicAdd(&us_f[s_lo + mt * 16 + 8 + g], c[2]);
                }
            }
        }
        __syncthreads();
        if (tid < nrows) us_inv[tid] = 1.0f / us_f[tid];
        __syncthreads();

        // ---- col phase: csW[j] += sum_i u_i P_ij ----
        for (int cp = 0; cp < 2; cp++) {
            const int j0 = (warp + cp * 32) * 16;
            for (int s = 0; s < nseg; s++) {
                const int s_lo = s ? s_break : 0;
                const int s_hi = s ? nrows : s_break;
                const int bh = bh0 + s;
                const int ntk = (s_hi - s_lo + 15) >> 4;
                float c0[4] = {0.f, 0.f, 0.f, 0.f};
                float c1[4] = {0.f, 0.f, 0.f, 0.f};
                for (int kt = 0; kt < ntk; kt++) {
                    const int k0 = s_lo + kt * 16;
                    const int ka = k0 + c2;
                    float f0 = (ka     < s_hi) ? us_inv[ka]     : 0.f;
                    float f1 = (ka + 1 < s_hi) ? us_inv[ka + 1] : 0.f;
                    float f2 = (ka + 8 < s_hi) ? us_inv[ka + 8] : 0.f;
                    float f3 = (ka + 9 < s_hi) ? us_inv[ka + 9] : 0.f;
                    unsigned a01 = packh2(f0, f1), a23 = packh2(f2, f3);
                    unsigned aa[4] = {a01, a01, a23, a23};
                    int rrow = min(k0 + l15, nrows - 1);
                    unsigned b0, b1, b2, b3;
                    ldsm4t(b0, b1, b2, b3, ps_base + sw_off(rrow, (j0 >> 3) + l16));
                    mma16816(c0, aa, b0, b1);
                    mma16816(c1, aa, b2, b3);
                }
                if (g == 0) {
                    float* cw = csW + (bh << 10) + j0;
                    atomicAdd(cw + c2,         c0[0]);
                    atomicAdd(cw + c2 + 1,     c0[1]);
                    atomicAdd(cw + 8 + c2,     c1[0]);
                    atomicAdd(cw + 8 + c2 + 1, c1[1]);
                }
            }
        }
        gsync();
    }

    // ---- tail: u writeback + g_vt = v_j * V^T for this block's rows ----
    const float* csF = g_cs3[NITERS % 3];
    for (int i = tid; i < nrows; i += 1024)
        g_ur[r0 + i] = us_inv[i];
    for (int d = warp; d < 64; d += 32) {
        for (int i = lane; i < nrows; i += 32) {
            int gr = r0 + i;
            int bh = gr >> 10, j = gr & 1023;
            float vf = 1.0f / csF[gr];
            float vv = g_v[(bh << 16) + (j << 6) + d];
            g_vt[(bh << 16) + (d << 10) + j] = __float2half_rn(vf * vv);
        }
    }
}

// ============================================================================
extern "C" void kernel_launch(void* const* d_in, const int* in_sizes, int n_in,
                              void* d_out, int out_size)
{
    const float* x  = (const float*)d_in[0];
    const float* Wq = (const float*)d_in[1];
    const float* bq = (const float*)d_in[2];
    const float* Wk = (const float*)d_in[3];
    const float* bk = (const float*)d_in[4];
    const float* Wv = (const float*)d_in[5];
    const float* bv = (const float*)d_in[6];
    const float* Wo = (const float*)d_in[7];
    const float* bo = (const float*)d_in[8];
    float* out = (float*)d_out;

    static int smem_set = 0;
    if (!smem_set) {
        cudaFuncSetAttribute(sinkhorn_tc,
                             cudaFuncAttributeMaxDynamicSharedMemorySize, SMEM_SZ);
        smem_set = 1;
    }

    conv_all<<<6208, 256>>>(x, Wq, Wk, Wv, Wo);              // 1
    qkv_h_kernel<<<dim3(8, 16, 3), 256>>>(bq, bk, bv);       // 2
    p_h_kernel<<<dim3(16, 8, NBH), 256>>>();                 // 3
    sinkhorn_tc<<<NBLOCKS, 1024, SMEM_SZ>>>();               // 4  <- profiled
    attnv_h_kernel<<<dim3(1, 8, NBH), 256>>>();              // 5
    out_h_kernel<<<dim3(16, 16, 1), 256>>>(bo, out);         // 6
}